// round 15
// baseline (speedup 1.0000x reference)
#include <cuda_runtime.h>
#include <cuda_fp16.h>
#include <cstdint>
#include <cstddef>

#define B_ 4
#define L_ 2048
#define D_ 1024
#define H_ 16
#define HD_ 64
#define NX (B_*L_*D_)

// Scratch (allocation-free rule: __device__ globals)
__device__ __half g_qh[NX];        // [b,h,l,hd] fp16, pre-scaled 0.125*log2(e)
__device__ __half g_kh[NX];        // [b,h,l,hd] fp16
__device__ __half g_vh[NX];        // [b,h,hd,l] fp16 (TRANSPOSED)
__device__ __half g_ao[NX];        // [b,l,d] fp16
__device__ __half g_xh[3][NX];     // fp16 q,k,v
__device__ __half g_wh[4][D_*D_];  // fp16 Wq,Wk,Wv,Wo

#define QSCALE 0.18033688011112042f   // 0.125 * log2(e)

// ---------------- helpers ----------------
__device__ __forceinline__ uint32_t s2u(const void* p) {
    uint32_t a;
    asm("{ .reg .u64 t; cvta.to.shared.u64 t, %1; cvt.u32.u64 %0, t; }" : "=r"(a) : "l"(p));
    return a;
}
__device__ __forceinline__ uint32_t pk2(float x, float y) {
    __half2 h = __floats2half2_rn(x, y);
    return *(uint32_t*)&h;
}
__device__ __forceinline__ float ex2f(float x) {
    float r; asm("ex2.approx.f32 %0, %1;" : "=f"(r) : "f"(x)); return r;
}
__device__ __forceinline__ void mma_f16(float* c, const uint32_t* a, const uint32_t* b) {
    asm volatile(
        "mma.sync.aligned.m16n8k16.row.col.f32.f16.f16.f32 "
        "{%0,%1,%2,%3}, {%4,%5,%6,%7}, {%8,%9}, {%0,%1,%2,%3};"
        : "+f"(c[0]), "+f"(c[1]), "+f"(c[2]), "+f"(c[3])
        : "r"(a[0]), "r"(a[1]), "r"(a[2]), "r"(a[3]), "r"(b[0]), "r"(b[1]));
}
__device__ __forceinline__ void ldm4(uint32_t& r0, uint32_t& r1, uint32_t& r2,
                                     uint32_t& r3, uint32_t addr) {
    asm volatile("ldmatrix.sync.aligned.m8n8.x4.shared.b16 {%0,%1,%2,%3}, [%4];"
                 : "=r"(r0), "=r"(r1), "=r"(r2), "=r"(r3) : "r"(addr));
}

// ---------------- fp16 convert pass (merged: q,k,v,Wq,Wk,Wv,Wo) ----------------
#define NXC (NX / 8)
#define WC  (D_ * D_ / 8)
#define CVT_ITEMS (3 * NXC + 4 * WC)

__global__ void __launch_bounds__(256) cvt_all(
        const float* __restrict__ q, const float* __restrict__ k,
        const float* __restrict__ v, const float* __restrict__ wq,
        const float* __restrict__ wk, const float* __restrict__ wv,
        const float* __restrict__ wo)
{
    int idx = blockIdx.x * 256 + threadIdx.x;
    if (idx >= CVT_ITEMS) return;
    const float* src;
    __half* dst;
    if (idx < 3 * NXC) {
        int z = idx / NXC;
        int off = idx - z * NXC;
        src = ((z == 0) ? q : (z == 1) ? k : v) + (size_t)off * 8;
        dst = g_xh[z] + (size_t)off * 8;
    } else {
        int t = idx - 3 * NXC;
        int w = t / WC;
        int off = t - w * WC;
        src = ((w == 0) ? wq : (w == 1) ? wk : (w == 2) ? wv : wo) + (size_t)off * 8;
        dst = g_wh[w] + (size_t)off * 8;
    }
    float4 a = *(const float4*)src;
    float4 b = *(const float4*)(src + 4);
    uint4 o;
    o.x = pk2(a.x, a.y); o.y = pk2(a.z, a.w);
    o.z = pk2(b.x, b.y); o.w = pk2(b.z, b.w);
    *(uint4*)dst = o;
}

// ---------------- fp16 mma.sync GEMM core: 3-stage pipeline, 1 barrier/iter ----------------
#define HP 72
#define SSZ (128 * HP)          // one operand, one stage (halves)
#define STG (2 * SSZ)           // A+B, one stage (halves)
#define GEMM_SMEM (3 * STG * 2) // 110592 bytes
#define NIT2 (D_ / 64)

struct GemmAcc { float a[2][8][4]; };

__device__ __forceinline__ void gemm_core(const __half* __restrict__ Xa,
                                          const __half* __restrict__ Wb,
                                          __half* sm, int tid, GemmAcc& acc)
{
    const int wid = tid >> 5, lane = tid & 31;
    const int wm = wid >> 1, wn = wid & 1;
    const int lr = lane & 7, lt = lane >> 3;
    const uint32_t offA = (((lt & 1) * 8 + lr) * HP + (lt >> 1) * 8) * 2;
    const uint32_t offB = (((lt >> 1) * 8 + lr) * HP + (lt & 1) * 8) * 2;

    #pragma unroll
    for (int am = 0; am < 2; am++)
        #pragma unroll
        for (int na = 0; na < 8; na++)
            #pragma unroll
            for (int q = 0; q < 4; q++) acc.a[am][na][q] = 0.f;

    auto load_stage = [&](int ck, int s) {
        __half* As = sm + s * STG;
        __half* Bs = As + SSZ;
        #pragma unroll
        for (int i = 0; i < 4; i++) {
            int id = tid + i * 256;
            int r = id >> 3, u = id & 7;
            asm volatile("cp.async.cg.shared.global [%0], [%1], 16;"
                         :: "r"(s2u(As + r * HP + u * 8)),
                            "l"(Xa + (size_t)r * D_ + ck * 64 + u * 8));
            asm volatile("cp.async.cg.shared.global [%0], [%1], 16;"
                         :: "r"(s2u(Bs + r * HP + u * 8)),
                            "l"(Wb + (size_t)r * D_ + ck * 64 + u * 8));
        }
        asm volatile("cp.async.commit_group;");
    };

    load_stage(0, 0);
    load_stage(1, 1);

    for (int it = 0; it < NIT2; it++) {
        asm volatile("cp.async.wait_group 1;");
        __syncthreads();
        if (it + 2 < NIT2) {
            load_stage(it + 2, (it + 2) % 3);
        } else {
            asm volatile("cp.async.commit_group;");
        }

        const __half* As = sm + (it % 3) * STG;
        const __half* Bs = As + SSZ;
        const uint32_t abase = s2u(As) + (uint32_t)(wm * 32 * HP) * 2 + offA;
        const uint32_t bbase = s2u(Bs) + (uint32_t)(wn * 64 * HP) * 2 + offB;

        #pragma unroll
        for (int kk = 0; kk < 4; kk++) {
            uint32_t a[2][4];
            ldm4(a[0][0], a[0][1], a[0][2], a[0][3], abase + kk * 32);
            ldm4(a[1][0], a[1][1], a[1][2], a[1][3], abase + 16 * HP * 2 + kk * 32);
            uint32_t b[8][2];
            #pragma unroll
            for (int j = 0; j < 4; j++) {
                uint32_t r0, r1, r2, r3;
                ldm4(r0, r1, r2, r3, bbase + j * 16 * HP * 2 + kk * 32);
                b[2 * j][0] = r0; b[2 * j][1] = r1;
                b[2 * j + 1][0] = r2; b[2 * j + 1][1] = r3;
            }
            #pragma unroll
            for (int am = 0; am < 2; am++)
                #pragma unroll
                for (int na = 0; na < 8; na++)
                    mma_f16(acc.a[am][na], a[am], b[na]);
        }
    }
    __syncthreads();
}

// Merged Q/K/V projection: grid (8, 64, 3). Writes fp16 head layouts.
// NOTE: no min-blocks clause -> ptxas free to use >128 regs and pipeline fragments.
__global__ void __launch_bounds__(256)
gemm_proj3()
{
    extern __shared__ __half smh[];
    const int tid = threadIdx.x;
    const int z = blockIdx.z;
    const int m0 = blockIdx.y * 128, n0 = blockIdx.x * 128;

    GemmAcc acc;
    gemm_core(g_xh[z] + (size_t)m0 * D_, g_wh[z] + (size_t)n0 * D_, smh, tid, acc);

    const int wid = tid >> 5, lane = tid & 31;
    const int wm = wid >> 1, wn = wid & 1;
    const int g = lane >> 2, t4 = lane & 3;
    const float scale = (z == 0) ? QSCALE : 1.0f;

    #pragma unroll
    for (int am = 0; am < 2; am++) {
        int r = m0 + wm * 32 + am * 16 + g;
        int b = r >> 11, l = r & 2047;
        #pragma unroll
        for (int na = 0; na < 8; na++) {
            int n = n0 + wn * 64 + na * 8 + 2 * t4;
            int h = n >> 6, hd = n & 63;
            if (z == 2) {
                __half* pv = g_vh + (((size_t)b * H_ + h) * HD_ + hd) * L_ + l;
                pv[0]      = __float2half_rn(acc.a[am][na][0]);
                pv[L_]     = __float2half_rn(acc.a[am][na][1]);
                pv[8]      = __float2half_rn(acc.a[am][na][2]);
                pv[L_ + 8] = __float2half_rn(acc.a[am][na][3]);
            } else {
                __half* Y = (z == 0) ? g_qh : g_kh;
                __half* p0 = Y + (((size_t)b * H_ + h) * L_ + l) * HD_ + hd;
                *(uint32_t*)p0 = pk2(acc.a[am][na][0] * scale, acc.a[am][na][1] * scale);
                __half* p1 = Y + (((size_t)b * H_ + h) * L_ + (l + 8)) * HD_ + hd;
                *(uint32_t*)p1 = pk2(acc.a[am][na][2] * scale, acc.a[am][na][3] * scale);
            }
        }
    }
}

// Output projection: fp16 in (g_ao, g_wh[3]), fp32 out.
__global__ void __launch_bounds__(256)
gemm_out(float* __restrict__ Y)
{
    extern __shared__ __half smh[];
    const int tid = threadIdx.x;
    const int m0 = blockIdx.y * 128, n0 = blockIdx.x * 128;

    GemmAcc acc;
    gemm_core(g_ao + (size_t)m0 * D_, g_wh[3] + (size_t)n0 * D_, smh, tid, acc);

    const int wid = tid >> 5, lane = tid & 31;
    const int wm = wid >> 1, wn = wid & 1;
    const int g = lane >> 2, t4 = lane & 3;

    #pragma unroll
    for (int am = 0; am < 2; am++) {
        int r = m0 + wm * 32 + am * 16 + g;
        #pragma unroll
        for (int na = 0; na < 8; na++) {
            int n = n0 + wn * 64 + na * 8 + 2 * t4;
            float* p0 = Y + (size_t)r * D_ + n;
            p0[0] = acc.a[am][na][0]; p0[1] = acc.a[am][na][1];
            float* p1 = Y + (size_t)(r + 8) * D_ + n;
            p1[0] = acc.a[am][na][2]; p1[1] = acc.a[am][na][3];
        }
    }
}

// ---------------- fp16 flash attention: 8 warps x 16 rows, masked-tile skip ----------------
#define KSTG (2 * 64 * HP)
#define ATTN_SMEM ((128 * HP + 2 * KSTG) * 2)
#define NBLK 296

__global__ void __launch_bounds__(256, 2) attn_mma(__half* __restrict__ ao)
{
    extern __shared__ __half smh[];
    __half* Qs = smh;
    __half* KV = smh + 128 * HP;

    const int tid = threadIdx.x;
    const int wid = tid >> 5, lane = tid & 31;
    const int g = lane >> 2, t4 = lane & 3;
    const int lr = lane & 7, lt = lane >> 3;
    const uint32_t offA = (((lt & 1) * 8 + lr) * HP + (lt >> 1) * 8) * 2;
    const uint32_t offB = (((lt >> 1) * 8 + lr) * HP + (lt & 1) * 8) * 2;
    const int p = blockIdx.x;

    const uint32_t qbase0 = s2u(Qs) + (uint32_t)(wid * 16 * HP) * 2 + offA;

    #pragma unroll 1
    for (int round = 0; round < 4; round++) {
        int rank = (round == 0) ? p
                 : (round == 1) ? (591 - p)
                 : (round == 2) ? (592 + p)
                 : (1183 - p);
        if (rank >= 1024) continue;
        const int qt = 15 - (rank >> 6);
        const int bh = rank & 63;
        const int q0 = qt * 128;

        const __half* Qb = g_qh + ((size_t)bh * L_ + q0) * HD_;
        const __half* Kb = g_kh + (size_t)bh * L_ * HD_;
        const __half* Vb = g_vh + (size_t)bh * HD_ * L_;

        __syncthreads();

        #pragma unroll
        for (int i = 0; i < 4; i++) {
            int e = tid + i * 256;
            int r = e >> 3, u = e & 7;
            *(uint4*)(Qs + r * HP + u * 8) =
                *(const uint4*)(Qb + (size_t)r * 64 + u * 8);
        }

        auto ldkv = [&](int kt, int st) {
            __half* Ks = KV + st * KSTG;
            __half* Vs = Ks + 64 * HP;
            const __half* kg = Kb + (size_t)kt * 64 * 64;
            const __half* vg = Vb + kt * 64;
            #pragma unroll
            for (int i = 0; i < 2; i++) {
                int e = tid + i * 256;
                int r = e >> 3, u = e & 7;
                asm volatile("cp.async.cg.shared.global [%0], [%1], 16;"
                             :: "r"(s2u(Ks + r * HP + u * 8)),
                                "l"(kg + (size_t)r * 64 + u * 8));
                asm volatile("cp.async.cg.shared.global [%0], [%1], 16;"
                             :: "r"(s2u(Vs + r * HP + u * 8)),
                                "l"(vg + (size_t)r * L_ + u * 8));
            }
            asm volatile("cp.async.commit_group;");
        };

        float mrun[2], lrun[2], O[8][4];
        #pragma unroll
        for (int i = 0; i < 2; i++) { mrun[i] = -1e30f; lrun[i] = 0.f; }
        #pragma unroll
        for (int nt = 0; nt < 8; nt++)
            #pragma unroll
            for (int e = 0; e < 4; e++) O[nt][e] = 0.f;

        const int ntiles = 2 * qt + 2;
        const int ntw = 2 * qt + 1 + (wid >= 4 ? 1 : 0);
        ldkv(0, 0);

        for (int kt = 0; kt < ntiles; kt++) {
            asm volatile("cp.async.wait_group 0;");
            __syncthreads();
            if (kt + 1 < ntiles) ldkv(kt + 1, (kt + 1) & 1);
            if (kt < ntw) {
                const __half* Ks = KV + (kt & 1) * KSTG;
                const __half* Vs = Ks + 64 * HP;
                const uint32_t kbase = s2u(Ks) + offB;
                const uint32_t vbase = s2u(Vs) + offB;

                float S[8][4];
                #pragma unroll
                for (int nt = 0; nt < 8; nt++)
                    #pragma unroll
                    for (int e = 0; e < 4; e++) S[nt][e] = 0.f;

                #pragma unroll
                for (int kc = 0; kc < 4; kc++) {
                    uint32_t af[4];
                    ldm4(af[0], af[1], af[2], af[3], qbase0 + kc * 32);
                    #pragma unroll
                    for (int j = 0; j < 4; j++) {
                        uint32_t r0, r1, r2, r3;
                        ldm4(r0, r1, r2, r3, kbase + j * 16 * HP * 2 + kc * 32);
                        uint32_t bf0[2] = {r0, r1}, bf1[2] = {r2, r3};
                        mma_f16(S[2 * j], af, bf0);
                        mma_f16(S[2 * j + 1], af, bf1);
                    }
                }

                const bool maskt = (kt == ntw - 1);
                uint32_t Ppk[8][2];
                #pragma unroll
                for (int rr = 0; rr < 2; rr++) {
                    float mloc = -1e30f;
                    if (maskt) {
                        const int rowg = q0 + wid * 16 + rr * 8 + g;
                        #pragma unroll
                        for (int nt = 0; nt < 8; nt++)
                            #pragma unroll
                            for (int e = 0; e < 2; e++) {
                                float vv = S[nt][rr * 2 + e];
                                if ((kt * 64 + nt * 8 + 2 * t4 + e) > rowg) vv = -1e30f;
                                S[nt][rr * 2 + e] = vv;
                                mloc = fmaxf(mloc, vv);
                            }
                    } else {
                        #pragma unroll
                        for (int nt = 0; nt < 8; nt++)
                            #pragma unroll
                            for (int e = 0; e < 2; e++)
                                mloc = fmaxf(mloc, S[nt][rr * 2 + e]);
                    }
                    mloc = fmaxf(mloc, __shfl_xor_sync(0xffffffffu, mloc, 1));
                    mloc = fmaxf(mloc, __shfl_xor_sync(0xffffffffu, mloc, 2));
                    float mnew = fmaxf(mrun[rr], mloc);
                    float corrf = ex2f(mrun[rr] - mnew);
                    float sum = 0.f;
                    #pragma unroll
                    for (int nt = 0; nt < 8; nt++) {
                        float p0 = ex2f(S[nt][rr * 2] - mnew);
                        float p1 = ex2f(S[nt][rr * 2 + 1] - mnew);
                        sum += p0; sum += p1;
                        Ppk[nt][rr] = pk2(p0, p1);
                    }
                    sum += __shfl_xor_sync(0xffffffffu, sum, 1);
                    sum += __shfl_xor_sync(0xffffffffu, sum, 2);
                    lrun[rr] = lrun[rr] * corrf + sum;
                    mrun[rr] = mnew;
                    #pragma unroll
                    for (int nt = 0; nt < 8; nt++)
                        #pragma unroll
                        for (int e = 0; e < 2; e++)
                            O[nt][rr * 2 + e] *= corrf;
                }

                #pragma unroll
                for (int kc = 0; kc < 4; kc++) {
                    uint32_t a[4];
                    a[0] = Ppk[2 * kc][0];
                    a[1] = Ppk[2 * kc][1];
                    a[2] = Ppk[2 * kc + 1][0];
                    a[3] = Ppk[2 * kc + 1][1];
                    #pragma unroll
                    for (int j = 0; j < 4; j++) {
                        uint32_t r0, r1, r2, r3;
                        ldm4(r0, r1, r2, r3, vbase + j * 16 * HP * 2 + kc * 32);
                        uint32_t bf0[2] = {r0, r1}, bf1[2] = {r2, r3};
                        mma_f16(O[2 * j], a, bf0);
                        mma_f16(O[2 * j + 1], a, bf1);
                    }
                }
            }
        }

        // ---- epilogue: normalize + fp16 write [b, l, d] ----
        const int b = bh >> 4, h = bh & 15;
        #pragma unroll
        for (int rr = 0; rr < 2; rr++) {
            float inv = 1.f / lrun[rr];
            int row = q0 + wid * 16 + rr * 8 + g;
            __half* op = ao + ((size_t)b * L_ + row) * D_ + h * 64 + 2 * t4;
            #pragma unroll
            for (int nt = 0; nt < 8; nt++)
                *(uint32_t*)(op + nt * 8) =
                    pk2(O[nt][rr * 2] * inv, O[nt][rr * 2 + 1] * inv);
        }
    }
}

// ---------------- launch ----------------
extern "C" void kernel_launch(void* const* d_in, const int* in_sizes, int n_in,
                              void* d_out, int out_size)
{
    const float* q  = (const float*)d_in[0];
    const float* k  = (const float*)d_in[1];
    const float* v  = (const float*)d_in[2];
    // d_in[3] = mask (causal tril) — applied analytically
    const float* Wq = (const float*)d_in[4];
    const float* Wk = (const float*)d_in[5];
    const float* Wv = (const float*)d_in[6];
    const float* Wo = (const float*)d_in[7];
    float* out = (float*)d_out;

    __half* ao;
    cudaGetSymbolAddress((void**)&ao, g_ao);

    cudaFuncSetAttribute(gemm_proj3, cudaFuncAttributeMaxDynamicSharedMemorySize, GEMM_SMEM);
    cudaFuncSetAttribute(gemm_out, cudaFuncAttributeMaxDynamicSharedMemorySize, GEMM_SMEM);
    cudaFuncSetAttribute(attn_mma, cudaFuncAttributeMaxDynamicSharedMemorySize, ATTN_SMEM);

    cvt_all<<<(CVT_ITEMS + 255) / 256, 256>>>(q, k, v, Wq, Wk, Wv, Wo);
    gemm_proj3<<<dim3(D_ / 128, (B_ * L_) / 128, 3), 256, GEMM_SMEM>>>();
    attn_mma<<<NBLK, 256, ATTN_SMEM>>>(ao);
    gemm_out<<<dim3(D_ / 128, (B_ * L_) / 128), 256, GEMM_SMEM>>>(out);
}

// round 16
// speedup vs baseline: 1.0210x; 1.0210x over previous
#include <cuda_runtime.h>
#include <cuda_fp16.h>
#include <cstdint>
#include <cstddef>

#define B_ 4
#define L_ 2048
#define D_ 1024
#define H_ 16
#define HD_ 64
#define NX (B_*L_*D_)

// Scratch (allocation-free rule: __device__ globals)
__device__ __half g_qh[NX];        // [b,h,l,hd] fp16, pre-scaled 0.125*log2(e)
__device__ __half g_kh[NX];        // [b,h,l,hd] fp16
__device__ __half g_vh[NX];        // [b,h,hd,l] fp16 (TRANSPOSED)
__device__ __half g_ao[NX];        // [b,l,d] fp16
__device__ __half g_xh[3][NX];     // fp16 q,k,v
__device__ __half g_wh[4][D_*D_];  // fp16 Wq,Wk,Wv,Wo

#define QSCALE 0.18033688011112042f   // 0.125 * log2(e)

// ---------------- helpers ----------------
__device__ __forceinline__ uint32_t s2u(const void* p) {
    uint32_t a;
    asm("{ .reg .u64 t; cvta.to.shared.u64 t, %1; cvt.u32.u64 %0, t; }" : "=r"(a) : "l"(p));
    return a;
}
__device__ __forceinline__ uint32_t pk2(float x, float y) {
    __half2 h = __floats2half2_rn(x, y);
    return *(uint32_t*)&h;
}
__device__ __forceinline__ float ex2f(float x) {
    float r; asm("ex2.approx.f32 %0, %1;" : "=f"(r) : "f"(x)); return r;
}
__device__ __forceinline__ void mma_f16(float* c, const uint32_t* a, const uint32_t* b) {
    asm volatile(
        "mma.sync.aligned.m16n8k16.row.col.f32.f16.f16.f32 "
        "{%0,%1,%2,%3}, {%4,%5,%6,%7}, {%8,%9}, {%0,%1,%2,%3};"
        : "+f"(c[0]), "+f"(c[1]), "+f"(c[2]), "+f"(c[3])
        : "r"(a[0]), "r"(a[1]), "r"(a[2]), "r"(a[3]), "r"(b[0]), "r"(b[1]));
}
__device__ __forceinline__ void ldm4(uint32_t& r0, uint32_t& r1, uint32_t& r2,
                                     uint32_t& r3, uint32_t addr) {
    asm volatile("ldmatrix.sync.aligned.m8n8.x4.shared.b16 {%0,%1,%2,%3}, [%4];"
                 : "=r"(r0), "=r"(r1), "=r"(r2), "=r"(r3) : "r"(addr));
}

// ---------------- fp16 convert pass (merged: q,k,v,Wq,Wk,Wv,Wo) ----------------
#define NXC (NX / 8)
#define WC  (D_ * D_ / 8)
#define CVT_ITEMS (3 * NXC + 4 * WC)

__global__ void __launch_bounds__(256) cvt_all(
        const float* __restrict__ q, const float* __restrict__ k,
        const float* __restrict__ v, const float* __restrict__ wq,
        const float* __restrict__ wk, const float* __restrict__ wv,
        const float* __restrict__ wo)
{
    int idx = blockIdx.x * 256 + threadIdx.x;
    if (idx >= CVT_ITEMS) return;
    const float* src;
    __half* dst;
    if (idx < 3 * NXC) {
        int z = idx / NXC;
        int off = idx - z * NXC;
        src = ((z == 0) ? q : (z == 1) ? k : v) + (size_t)off * 8;
        dst = g_xh[z] + (size_t)off * 8;
    } else {
        int t = idx - 3 * NXC;
        int w = t / WC;
        int off = t - w * WC;
        src = ((w == 0) ? wq : (w == 1) ? wk : (w == 2) ? wv : wo) + (size_t)off * 8;
        dst = g_wh[w] + (size_t)off * 8;
    }
    float4 a = *(const float4*)src;
    float4 b = *(const float4*)(src + 4);
    uint4 o;
    o.x = pk2(a.x, a.y); o.y = pk2(a.z, a.w);
    o.z = pk2(b.x, b.y); o.w = pk2(b.z, b.w);
    *(uint4*)dst = o;
}

// ---------------- fp16 mma.sync GEMM core: 3-stage pipeline, 1 barrier/iter ----------------
#define HP 72
#define SSZ (128 * HP)          // one operand, one stage (halves)
#define STG (2 * SSZ)           // A+B, one stage (halves)
#define GEMM_SMEM (3 * STG * 2) // 110592 bytes
#define NIT2 (D_ / 64)

struct GemmAcc { float a[2][8][4]; };

__device__ __forceinline__ void gemm_core(const __half* __restrict__ Xa,
                                          const __half* __restrict__ Wb,
                                          __half* sm, int tid, GemmAcc& acc)
{
    const int wid = tid >> 5, lane = tid & 31;
    const int wm = wid >> 1, wn = wid & 1;
    const int lr = lane & 7, lt = lane >> 3;
    const uint32_t offA = (((lt & 1) * 8 + lr) * HP + (lt >> 1) * 8) * 2;
    const uint32_t offB = (((lt >> 1) * 8 + lr) * HP + (lt & 1) * 8) * 2;

    #pragma unroll
    for (int am = 0; am < 2; am++)
        #pragma unroll
        for (int na = 0; na < 8; na++)
            #pragma unroll
            for (int q = 0; q < 4; q++) acc.a[am][na][q] = 0.f;

    auto load_stage = [&](int ck, int s) {
        __half* As = sm + s * STG;
        __half* Bs = As + SSZ;
        #pragma unroll
        for (int i = 0; i < 4; i++) {
            int id = tid + i * 256;
            int r = id >> 3, u = id & 7;
            asm volatile("cp.async.cg.shared.global [%0], [%1], 16;"
                         :: "r"(s2u(As + r * HP + u * 8)),
                            "l"(Xa + (size_t)r * D_ + ck * 64 + u * 8));
            asm volatile("cp.async.cg.shared.global [%0], [%1], 16;"
                         :: "r"(s2u(Bs + r * HP + u * 8)),
                            "l"(Wb + (size_t)r * D_ + ck * 64 + u * 8));
        }
        asm volatile("cp.async.commit_group;");
    };

    load_stage(0, 0);
    load_stage(1, 1);

    for (int it = 0; it < NIT2; it++) {
        asm volatile("cp.async.wait_group 1;");
        __syncthreads();
        if (it + 2 < NIT2) {
            load_stage(it + 2, (it + 2) % 3);
        } else {
            asm volatile("cp.async.commit_group;");
        }

        const __half* As = sm + (it % 3) * STG;
        const __half* Bs = As + SSZ;
        const uint32_t abase = s2u(As) + (uint32_t)(wm * 32 * HP) * 2 + offA;
        const uint32_t bbase = s2u(Bs) + (uint32_t)(wn * 64 * HP) * 2 + offB;

        #pragma unroll
        for (int kk = 0; kk < 4; kk++) {
            uint32_t a[2][4];
            ldm4(a[0][0], a[0][1], a[0][2], a[0][3], abase + kk * 32);
            ldm4(a[1][0], a[1][1], a[1][2], a[1][3], abase + 16 * HP * 2 + kk * 32);
            uint32_t b[8][2];
            #pragma unroll
            for (int j = 0; j < 4; j++) {
                uint32_t r0, r1, r2, r3;
                ldm4(r0, r1, r2, r3, bbase + j * 16 * HP * 2 + kk * 32);
                b[2 * j][0] = r0; b[2 * j][1] = r1;
                b[2 * j + 1][0] = r2; b[2 * j + 1][1] = r3;
            }
            #pragma unroll
            for (int am = 0; am < 2; am++)
                #pragma unroll
                for (int na = 0; na < 8; na++)
                    mma_f16(acc.a[am][na], a[am], b[na]);
        }
    }
    __syncthreads();
}

// Merged Q/K/V projection: grid (8, 64, 3). Writes fp16 head layouts.
__global__ void __launch_bounds__(256, 2)
gemm_proj3()
{
    extern __shared__ __half smh[];
    const int tid = threadIdx.x;
    const int z = blockIdx.z;
    const int m0 = blockIdx.y * 128, n0 = blockIdx.x * 128;

    GemmAcc acc;
    gemm_core(g_xh[z] + (size_t)m0 * D_, g_wh[z] + (size_t)n0 * D_, smh, tid, acc);

    const int wid = tid >> 5, lane = tid & 31;
    const int wm = wid >> 1, wn = wid & 1;
    const int g = lane >> 2, t4 = lane & 3;
    const float scale = (z == 0) ? QSCALE : 1.0f;

    #pragma unroll
    for (int am = 0; am < 2; am++) {
        int r = m0 + wm * 32 + am * 16 + g;
        int b = r >> 11, l = r & 2047;
        #pragma unroll
        for (int na = 0; na < 8; na++) {
            int n = n0 + wn * 64 + na * 8 + 2 * t4;
            int h = n >> 6, hd = n & 63;
            if (z == 2) {
                __half* pv = g_vh + (((size_t)b * H_ + h) * HD_ + hd) * L_ + l;
                pv[0]      = __float2half_rn(acc.a[am][na][0]);
                pv[L_]     = __float2half_rn(acc.a[am][na][1]);
                pv[8]      = __float2half_rn(acc.a[am][na][2]);
                pv[L_ + 8] = __float2half_rn(acc.a[am][na][3]);
            } else {
                __half* Y = (z == 0) ? g_qh : g_kh;
                __half* p0 = Y + (((size_t)b * H_ + h) * L_ + l) * HD_ + hd;
                *(uint32_t*)p0 = pk2(acc.a[am][na][0] * scale, acc.a[am][na][1] * scale);
                __half* p1 = Y + (((size_t)b * H_ + h) * L_ + (l + 8)) * HD_ + hd;
                *(uint32_t*)p1 = pk2(acc.a[am][na][2] * scale, acc.a[am][na][3] * scale);
            }
        }
    }
}

// Output projection: fp16 in (g_ao, g_wh[3]), fp32 out.
__global__ void __launch_bounds__(256, 2)
gemm_out(float* __restrict__ Y)
{
    extern __shared__ __half smh[];
    const int tid = threadIdx.x;
    const int m0 = blockIdx.y * 128, n0 = blockIdx.x * 128;

    GemmAcc acc;
    gemm_core(g_ao + (size_t)m0 * D_, g_wh[3] + (size_t)n0 * D_, smh, tid, acc);

    const int wid = tid >> 5, lane = tid & 31;
    const int wm = wid >> 1, wn = wid & 1;
    const int g = lane >> 2, t4 = lane & 3;

    #pragma unroll
    for (int am = 0; am < 2; am++) {
        int r = m0 + wm * 32 + am * 16 + g;
        #pragma unroll
        for (int na = 0; na < 8; na++) {
            int n = n0 + wn * 64 + na * 8 + 2 * t4;
            float* p0 = Y + (size_t)r * D_ + n;
            p0[0] = acc.a[am][na][0]; p0[1] = acc.a[am][na][1];
            float* p1 = Y + (size_t)(r + 8) * D_ + n;
            p1[0] = acc.a[am][na][2]; p1[1] = acc.a[am][na][3];
        }
    }
}

// ---------------- fp16 flash attention: 8 warps x 16 rows, masked-tile skip ----------------
#define KSTG (2 * 64 * HP)
#define ATTN_SMEM ((128 * HP + 2 * KSTG) * 2)
#define NBLK 296

__global__ void __launch_bounds__(256, 2) attn_mma(__half* __restrict__ ao)
{
    extern __shared__ __half smh[];
    __half* Qs = smh;
    __half* KV = smh + 128 * HP;

    const int tid = threadIdx.x;
    const int wid = tid >> 5, lane = tid & 31;
    const int g = lane >> 2, t4 = lane & 3;
    const int lr = lane & 7, lt = lane >> 3;
    const uint32_t offA = (((lt & 1) * 8 + lr) * HP + (lt >> 1) * 8) * 2;
    const uint32_t offB = (((lt >> 1) * 8 + lr) * HP + (lt & 1) * 8) * 2;
    const int p = blockIdx.x;

    const uint32_t qbase0 = s2u(Qs) + (uint32_t)(wid * 16 * HP) * 2 + offA;

    #pragma unroll 1
    for (int round = 0; round < 4; round++) {
        int rank = (round == 0) ? p
                 : (round == 1) ? (591 - p)
                 : (round == 2) ? (592 + p)
                 : (1183 - p);
        if (rank >= 1024) continue;
        const int qt = 15 - (rank >> 6);
        const int bh = rank & 63;
        const int q0 = qt * 128;

        const __half* Qb = g_qh + ((size_t)bh * L_ + q0) * HD_;
        const __half* Kb = g_kh + (size_t)bh * L_ * HD_;
        const __half* Vb = g_vh + (size_t)bh * HD_ * L_;

        __syncthreads();

        // Q tile via cp.async (overlapped with first KV load; covered by
        // wait_group 0 + barrier at iteration 0)
        #pragma unroll
        for (int i = 0; i < 4; i++) {
            int e = tid + i * 256;
            int r = e >> 3, u = e & 7;
            asm volatile("cp.async.cg.shared.global [%0], [%1], 16;"
                         :: "r"(s2u(Qs + r * HP + u * 8)),
                            "l"(Qb + (size_t)r * 64 + u * 8));
        }
        asm volatile("cp.async.commit_group;");

        auto ldkv = [&](int kt, int st) {
            __half* Ks = KV + st * KSTG;
            __half* Vs = Ks + 64 * HP;
            const __half* kg = Kb + (size_t)kt * 64 * 64;
            const __half* vg = Vb + kt * 64;
            #pragma unroll
            for (int i = 0; i < 2; i++) {
                int e = tid + i * 256;
                int r = e >> 3, u = e & 7;
                asm volatile("cp.async.cg.shared.global [%0], [%1], 16;"
                             :: "r"(s2u(Ks + r * HP + u * 8)),
                                "l"(kg + (size_t)r * 64 + u * 8));
                asm volatile("cp.async.cg.shared.global [%0], [%1], 16;"
                             :: "r"(s2u(Vs + r * HP + u * 8)),
                                "l"(vg + (size_t)r * L_ + u * 8));
            }
            asm volatile("cp.async.commit_group;");
        };

        float mrun[2], lrun[2], O[8][4];
        #pragma unroll
        for (int i = 0; i < 2; i++) { mrun[i] = -1e30f; lrun[i] = 0.f; }
        #pragma unroll
        for (int nt = 0; nt < 8; nt++)
            #pragma unroll
            for (int e = 0; e < 4; e++) O[nt][e] = 0.f;

        const int ntiles = 2 * qt + 2;
        const int ntw = 2 * qt + 1 + (wid >= 4 ? 1 : 0);
        ldkv(0, 0);

        for (int kt = 0; kt < ntiles; kt++) {
            asm volatile("cp.async.wait_group 0;");
            __syncthreads();
            if (kt + 1 < ntiles) ldkv(kt + 1, (kt + 1) & 1);
            if (kt < ntw) {
                const __half* Ks = KV + (kt & 1) * KSTG;
                const __half* Vs = Ks + 64 * HP;
                const uint32_t kbase = s2u(Ks) + offB;
                const uint32_t vbase = s2u(Vs) + offB;

                float S[8][4];
                #pragma unroll
                for (int nt = 0; nt < 8; nt++)
                    #pragma unroll
                    for (int e = 0; e < 4; e++) S[nt][e] = 0.f;

                #pragma unroll
                for (int kc = 0; kc < 4; kc++) {
                    uint32_t af[4];
                    ldm4(af[0], af[1], af[2], af[3], qbase0 + kc * 32);
                    #pragma unroll
                    for (int j = 0; j < 4; j++) {
                        uint32_t r0, r1, r2, r3;
                        ldm4(r0, r1, r2, r3, kbase + j * 16 * HP * 2 + kc * 32);
                        uint32_t bf0[2] = {r0, r1}, bf1[2] = {r2, r3};
                        mma_f16(S[2 * j], af, bf0);
                        mma_f16(S[2 * j + 1], af, bf1);
                    }
                }

                const bool maskt = (kt == ntw - 1);
                uint32_t Ppk[8][2];
                #pragma unroll
                for (int rr = 0; rr < 2; rr++) {
                    float mloc = -1e30f;
                    if (maskt) {
                        const int rowg = q0 + wid * 16 + rr * 8 + g;
                        #pragma unroll
                        for (int nt = 0; nt < 8; nt++)
                            #pragma unroll
                            for (int e = 0; e < 2; e++) {
                                float vv = S[nt][rr * 2 + e];
                                if ((kt * 64 + nt * 8 + 2 * t4 + e) > rowg) vv = -1e30f;
                                S[nt][rr * 2 + e] = vv;
                                mloc = fmaxf(mloc, vv);
                            }
                    } else {
                        #pragma unroll
                        for (int nt = 0; nt < 8; nt++)
                            #pragma unroll
                            for (int e = 0; e < 2; e++)
                                mloc = fmaxf(mloc, S[nt][rr * 2 + e]);
                    }
                    mloc = fmaxf(mloc, __shfl_xor_sync(0xffffffffu, mloc, 1));
                    mloc = fmaxf(mloc, __shfl_xor_sync(0xffffffffu, mloc, 2));
                    float mnew = fmaxf(mrun[rr], mloc);
                    float corrf = ex2f(mrun[rr] - mnew);
                    float sum = 0.f;
                    #pragma unroll
                    for (int nt = 0; nt < 8; nt++) {
                        float p0 = ex2f(S[nt][rr * 2] - mnew);
                        float p1 = ex2f(S[nt][rr * 2 + 1] - mnew);
                        sum += p0; sum += p1;
                        Ppk[nt][rr] = pk2(p0, p1);
                    }
                    sum += __shfl_xor_sync(0xffffffffu, sum, 1);
                    sum += __shfl_xor_sync(0xffffffffu, sum, 2);
                    lrun[rr] = lrun[rr] * corrf + sum;
                    mrun[rr] = mnew;
                    #pragma unroll
                    for (int nt = 0; nt < 8; nt++)
                        #pragma unroll
                        for (int e = 0; e < 2; e++)
                            O[nt][rr * 2 + e] *= corrf;
                }

                #pragma unroll
                for (int kc = 0; kc < 4; kc++) {
                    uint32_t a[4];
                    a[0] = Ppk[2 * kc][0];
                    a[1] = Ppk[2 * kc][1];
                    a[2] = Ppk[2 * kc + 1][0];
                    a[3] = Ppk[2 * kc + 1][1];
                    #pragma unroll
                    for (int j = 0; j < 4; j++) {
                        uint32_t r0, r1, r2, r3;
                        ldm4(r0, r1, r2, r3, vbase + j * 16 * HP * 2 + kc * 32);
                        uint32_t bf0[2] = {r0, r1}, bf1[2] = {r2, r3};
                        mma_f16(O[2 * j], a, bf0);
                        mma_f16(O[2 * j + 1], a, bf1);
                    }
                }
            }
        }

        // ---- epilogue: normalize + fp16 write [b, l, d] ----
        const int b = bh >> 4, h = bh & 15;
        #pragma unroll
        for (int rr = 0; rr < 2; rr++) {
            float inv = 1.f / lrun[rr];
            int row = q0 + wid * 16 + rr * 8 + g;
            __half* op = ao + ((size_t)b * L_ + row) * D_ + h * 64 + 2 * t4;
            #pragma unroll
            for (int nt = 0; nt < 8; nt++)
                *(uint32_t*)(op + nt * 8) =
                    pk2(O[nt][rr * 2] * inv, O[nt][rr * 2 + 1] * inv);
        }
    }
}

// ---------------- launch ----------------
extern "C" void kernel_launch(void* const* d_in, const int* in_sizes, int n_in,
                              void* d_out, int out_size)
{
    const float* q  = (const float*)d_in[0];
    const float* k  = (const float*)d_in[1];
    const float* v  = (const float*)d_in[2];
    // d_in[3] = mask (causal tril) — applied analytically
    const float* Wq = (const float*)d_in[4];
    const float* Wk = (const float*)d_in[5];
    const float* Wv = (const float*)d_in[6];
    const float* Wo = (const float*)d_in[7];
    float* out = (float*)d_out;

    __half* ao;
    cudaGetSymbolAddress((void**)&ao, g_ao);

    cudaFuncSetAttribute(gemm_proj3, cudaFuncAttributeMaxDynamicSharedMemorySize, GEMM_SMEM);
    cudaFuncSetAttribute(gemm_out, cudaFuncAttributeMaxDynamicSharedMemorySize, GEMM_SMEM);
    cudaFuncSetAttribute(attn_mma, cudaFuncAttributeMaxDynamicSharedMemorySize, ATTN_SMEM);

    cvt_all<<<(CVT_ITEMS + 255) / 256, 256>>>(q, k, v, Wq, Wk, Wv, Wo);
    gemm_proj3<<<dim3(D_ / 128, (B_ * L_) / 128, 3), 256, GEMM_SMEM>>>();
    attn_mma<<<NBLK, 256, ATTN_SMEM>>>(ao);
    gemm_out<<<dim3(D_ / 128, (B_ * L_) / 128), 256, GEMM_SMEM>>>(out);
}